// round 1
// baseline (speedup 1.0000x reference)
#include <cuda_runtime.h>
#include <math.h>
#include <stdint.h>

// Problem constants
#define LL   8
#define DD   512
#define HH   8
#define DHH  64
#define SS   64
#define VV   66
#define BB   256
#define MM   (BB * SS)      // 16384 token rows
#define DFF  (4 * DD)       // 2048

// ---------------- scratch (static device allocations; no cudaMalloc) -------
__device__ float g_x[MM * DD];
__device__ float g_h[MM * DD];
__device__ float g_q[MM * DD];
__device__ float g_k[MM * DD];
__device__ float g_v[MM * DD];
__device__ float g_o[MM * DD];
__device__ float g_hid[MM * DFF];
__device__ float g_logits[MM * VV];
__device__ float g_loss;

// ---------------- embedding + loss-accumulator reset -----------------------
__global__ void __launch_bounds__(256) embed_kernel(
    const int* __restrict__ ids, const float* __restrict__ tok,
    const float* __restrict__ pos, float* __restrict__ x)
{
    int i = blockIdx.x * 256 + threadIdx.x;
    if (i == 0) g_loss = 0.0f;
    if (i >= MM * DD) return;
    int row = i / DD;
    int d   = i - row * DD;
    int s   = row % SS;
    x[i] = tok[(size_t)ids[row] * DD + d] + pos[(size_t)s * DD + d];
}

// ---------------- LayerNorm (unbiased std, eps added to std) ---------------
__global__ void __launch_bounds__(128) ln_kernel(
    const float* __restrict__ x, const float* __restrict__ g,
    const float* __restrict__ b, float* __restrict__ out)
{
    int row = blockIdx.x;
    int t   = threadIdx.x;                 // 0..127 ; D/4 = 128 float4
    const float4* xr = (const float4*)(x + (size_t)row * DD);
    float4 v = xr[t];
    float s  = v.x + v.y + v.z + v.w;
    float ss = v.x * v.x + v.y * v.y + v.z * v.z + v.w * v.w;

    #pragma unroll
    for (int o = 16; o; o >>= 1) {
        s  += __shfl_xor_sync(0xffffffffu, s,  o);
        ss += __shfl_xor_sync(0xffffffffu, ss, o);
    }
    __shared__ float sh[8];
    int wid = t >> 5, lane = t & 31;
    if (lane == 0) { sh[wid * 2] = s; sh[wid * 2 + 1] = ss; }
    __syncthreads();
    s  = sh[0] + sh[2] + sh[4] + sh[6];
    ss = sh[1] + sh[3] + sh[5] + sh[7];

    float mean = s * (1.0f / DD);
    float var  = (ss - s * mean) * (1.0f / (DD - 1));
    float inv  = 1.0f / (sqrtf(fmaxf(var, 0.0f)) + 1e-10f);

    const float4* gr = (const float4*)g;
    const float4* br = (const float4*)b;
    float4 gv = gr[t], bv = br[t];
    float4 ov;
    ov.x = (v.x - mean) * inv * gv.x + bv.x;
    ov.y = (v.y - mean) * inv * gv.y + bv.y;
    ov.z = (v.z - mean) * inv * gv.z + bv.z;
    ov.w = (v.w - mean) * inv * gv.w + bv.w;
    ((float4*)(out + (size_t)row * DD))[t] = ov;
}

// ---------------- SGEMM 128x128x8, 8x8 microtile ---------------------------
// C[M,N] = A[M,K] @ B[K,N]  (+ bias[N]) (+ res[M,N]) (gelu)
template<bool GELU, bool RES, bool BIAS>
__global__ void __launch_bounds__(256) sgemm(
    int M, int N, int K,
    const float* __restrict__ A, const float* __restrict__ Bm,
    const float* __restrict__ bias, const float* __restrict__ res,
    float* __restrict__ C)
{
    constexpr int BM = 128, BN = 128, BK = 8;
    __shared__ float As[BK][BM];
    __shared__ float Bs[BK][BN];

    int tid  = threadIdx.x;
    int tx   = tid & 15;        // 0..15
    int ty   = tid >> 4;        // 0..15
    int brow = blockIdx.y * BM;
    int bcol = blockIdx.x * BN;

    float acc[8][8];
    #pragma unroll
    for (int i = 0; i < 8; i++)
        #pragma unroll
        for (int j = 0; j < 8; j++) acc[i][j] = 0.0f;

    int aRow = tid >> 1;            // 0..127
    int aCol = (tid & 1) * 4;       // 0 or 4
    int bRow = tid >> 5;            // 0..7
    int bCol = (tid & 31) * 4;      // 0..124

    const float* Aptr = A  + (size_t)(brow + aRow) * K + aCol;
    const float* Bptr = Bm + (size_t)bRow * N + bcol + bCol;

    for (int k0 = 0; k0 < K; k0 += BK) {
        float4 a4 = *(const float4*)(Aptr + k0);
        float4 b4 = *(const float4*)(Bptr + (size_t)k0 * N);
        As[aCol + 0][aRow] = a4.x;
        As[aCol + 1][aRow] = a4.y;
        As[aCol + 2][aRow] = a4.z;
        As[aCol + 3][aRow] = a4.w;
        *(float4*)&Bs[bRow][bCol] = b4;
        __syncthreads();

        #pragma unroll
        for (int k = 0; k < BK; k++) {
            float4 a0 = *(const float4*)&As[k][ty * 8];
            float4 a1 = *(const float4*)&As[k][ty * 8 + 4];
            float4 b0 = *(const float4*)&Bs[k][tx * 8];
            float4 b1 = *(const float4*)&Bs[k][tx * 8 + 4];
            float av[8] = {a0.x, a0.y, a0.z, a0.w, a1.x, a1.y, a1.z, a1.w};
            float bv[8] = {b0.x, b0.y, b0.z, b0.w, b1.x, b1.y, b1.z, b1.w};
            #pragma unroll
            for (int i = 0; i < 8; i++)
                #pragma unroll
                for (int j = 0; j < 8; j++)
                    acc[i][j] = fmaf(av[i], bv[j], acc[i][j]);
        }
        __syncthreads();
    }

    #pragma unroll
    for (int i = 0; i < 8; i++) {
        int row = brow + ty * 8 + i;
        #pragma unroll
        for (int j = 0; j < 8; j++) {
            int col = bcol + tx * 8 + j;
            float vv = acc[i][j];
            if (BIAS) vv += bias[col];
            if (RES)  vv += res[(size_t)row * N + col];
            if (GELU) vv = 0.5f * vv * (1.0f + erff(vv * 0.70710678118654752f));
            C[(size_t)row * N + col] = vv;
        }
    }
}

// ---------------- fused causal attention per (b,h) -------------------------
__global__ void __launch_bounds__(256) attn_kernel(
    const float* __restrict__ q, const float* __restrict__ k,
    const float* __restrict__ v, float* __restrict__ o)
{
    int bh = blockIdx.x;
    int b  = bh >> 3;
    int h  = bh & 7;
    const float* qb = q + (size_t)b * SS * DD + h * DHH;
    const float* kb = k + (size_t)b * SS * DD + h * DHH;
    const float* vb = v + (size_t)b * SS * DD + h * DHH;
    float*       ob = o + (size_t)b * SS * DD + h * DHH;

    __shared__ float Ks[SS][DHH + 1];
    __shared__ float Vs[SS][DHH + 1];
    __shared__ float attn_s[8][SS];

    int tid = threadIdx.x;
    for (int i = tid; i < SS * DHH; i += 256) {
        int s = i >> 6, e = i & 63;
        Ks[s][e] = kb[(size_t)s * DD + e];
        Vs[s][e] = vb[(size_t)s * DD + e];
    }
    __syncthreads();

    int warp = tid >> 5, lane = tid & 31;
    const float scale = 0.044194173824159216f;  // 1/sqrt(512) (1/sqrt(d_model))

    for (int r = 0; r < 8; r++) {
        int s = warp * 8 + r;
        float q0 = qb[(size_t)s * DD + lane];
        float q1 = qb[(size_t)s * DD + lane + 32];

        float sc0 = 0.0f, sc1 = 0.0f;
        #pragma unroll
        for (int e = 0; e < 32; e++) {
            float qe = __shfl_sync(0xffffffffu, q0, e);
            sc0 = fmaf(qe, Ks[lane][e],      sc0);
            sc1 = fmaf(qe, Ks[lane + 32][e], sc1);
        }
        #pragma unroll
        for (int e = 0; e < 32; e++) {
            float qe = __shfl_sync(0xffffffffu, q1, e);
            sc0 = fmaf(qe, Ks[lane][e + 32],      sc0);
            sc1 = fmaf(qe, Ks[lane + 32][e + 32], sc1);
        }
        sc0 = (lane <= s)      ? sc0 * scale : -1e30f;
        sc1 = (lane + 32 <= s) ? sc1 * scale : -1e30f;

        float m = fmaxf(sc0, sc1);
        #pragma unroll
        for (int off = 16; off; off >>= 1)
            m = fmaxf(m, __shfl_xor_sync(0xffffffffu, m, off));
        float e0 = __expf(sc0 - m), e1 = __expf(sc1 - m);
        float sum = e0 + e1;
        #pragma unroll
        for (int off = 16; off; off >>= 1)
            sum += __shfl_xor_sync(0xffffffffu, sum, off);
        float inv = 1.0f / sum;
        attn_s[warp][lane]      = e0 * inv;
        attn_s[warp][lane + 32] = e1 * inv;
        __syncwarp();

        float o0 = 0.0f, o1 = 0.0f;
        #pragma unroll
        for (int t = 0; t < SS; t++) {
            float a = attn_s[warp][t];
            o0 = fmaf(a, Vs[t][lane],      o0);
            o1 = fmaf(a, Vs[t][lane + 32], o1);
        }
        ob[(size_t)s * DD + lane]      = o0;
        ob[(size_t)s * DD + lane + 32] = o1;
        __syncwarp();
    }
}

// ---------------- unembed: logits = x @ Wu + bu ----------------------------
__global__ void __launch_bounds__(128) unembed_kernel(
    const float* __restrict__ x, const float* __restrict__ Wu,
    const float* __restrict__ bu, float* __restrict__ logits)
{
    __shared__ float xs[DD];
    int row = blockIdx.x;
    for (int i = threadIdx.x; i < DD; i += 128)
        xs[i] = x[(size_t)row * DD + i];
    __syncthreads();
    int n = threadIdx.x;
    if (n < VV) {
        float acc = bu[n];
        #pragma unroll 8
        for (int kk = 0; kk < DD; kk++)
            acc = fmaf(xs[kk], Wu[(size_t)kk * VV + n], acc);
        logits[(size_t)row * VV + n] = acc;
    }
}

// ---------------- cross-entropy loss (one warp per row) --------------------
__global__ void __launch_bounds__(128) loss_kernel(
    const float* __restrict__ logits, const int* __restrict__ tgt)
{
    int warp = threadIdx.x >> 5, lane = threadIdx.x & 31;
    int row  = blockIdx.x * 4 + warp;
    const float* lr = logits + (size_t)row * VV;

    float l0 = lr[lane];
    float l1 = lr[lane + 32];
    float l2 = (lane + 64 < VV) ? lr[lane + 64] : -1e30f;

    float m = fmaxf(fmaxf(l0, l1), l2);
    #pragma unroll
    for (int off = 16; off; off >>= 1)
        m = fmaxf(m, __shfl_xor_sync(0xffffffffu, m, off));
    float sum = expf(l0 - m) + expf(l1 - m) + ((lane + 64 < VV) ? expf(l2 - m) : 0.0f);
    #pragma unroll
    for (int off = 16; off; off >>= 1)
        sum += __shfl_xor_sync(0xffffffffu, sum, off);

    if (lane == 0) {
        float lse = m + logf(sum);
        float lt  = lr[tgt[row]];
        atomicAdd(&g_loss, lse - lt);
    }
}

// ---------------- output assembly ------------------------------------------
__global__ void __launch_bounds__(256) copy_out_kernel(
    const float* __restrict__ lg, float* __restrict__ out, int n)
{
    int i = blockIdx.x * 256 + threadIdx.x;
    if (i < n) out[i] = lg[i];
}

__global__ void __launch_bounds__(128) write_loss_kernel(
    float* __restrict__ out, int lo, int hi)
{
    int i = lo + blockIdx.x * 128 + threadIdx.x;
    if (i < hi) out[i] = g_loss * (1.0f / (float)MM);
}

// ---------------- launcher --------------------------------------------------
extern "C" void kernel_launch(void* const* d_in, const int* in_sizes, int n_in,
                              void* d_out, int out_size)
{
    const int*   ids  = (const int*)d_in[0];
    const int*   tgt  = (const int*)d_in[1];
    const float* tok  = (const float*)d_in[2];
    const float* pos  = (const float*)d_in[3];
    const float* Wq   = (const float*)d_in[4];
    const float* Wk   = (const float*)d_in[5];
    const float* Wv   = (const float*)d_in[6];
    const float* Wo   = (const float*)d_in[7];
    const float* bo   = (const float*)d_in[8];
    const float* W1   = (const float*)d_in[9];
    const float* b1   = (const float*)d_in[10];
    const float* W2   = (const float*)d_in[11];
    const float* b2   = (const float*)d_in[12];
    const float* ln1g = (const float*)d_in[13];
    const float* ln1b = (const float*)d_in[14];
    const float* ln2g = (const float*)d_in[15];
    const float* ln2b = (const float*)d_in[16];
    const float* lnfg = (const float*)d_in[17];
    const float* lnfb = (const float*)d_in[18];
    const float* Wu   = (const float*)d_in[19];
    const float* bu   = (const float*)d_in[20];
    float* out = (float*)d_out;

    float *x, *h, *qb, *kb, *vb, *ob, *hid, *lg;
    cudaGetSymbolAddress((void**)&x,   g_x);
    cudaGetSymbolAddress((void**)&h,   g_h);
    cudaGetSymbolAddress((void**)&qb,  g_q);
    cudaGetSymbolAddress((void**)&kb,  g_k);
    cudaGetSymbolAddress((void**)&vb,  g_v);
    cudaGetSymbolAddress((void**)&ob,  g_o);
    cudaGetSymbolAddress((void**)&hid, g_hid);
    cudaGetSymbolAddress((void**)&lg,  g_logits);

    embed_kernel<<<(MM * DD + 255) / 256, 256>>>(ids, tok, pos, x);

    dim3 gD(DD / 128, MM / 128);     // N=512 GEMMs
    dim3 gF(DFF / 128, MM / 128);    // N=2048 GEMM

    for (int l = 0; l < LL; l++) {
        size_t wOff  = (size_t)l * DD * DD;
        size_t w1Off = (size_t)l * DD * DFF;
        size_t w2Off = (size_t)l * DFF * DD;

        ln_kernel<<<MM, 128>>>(x, ln1g + l * DD, ln1b + l * DD, h);

        sgemm<false, false, false><<<gD, 256>>>(MM, DD, DD, h, Wq + wOff, nullptr, nullptr, qb);
        sgemm<false, false, false><<<gD, 256>>>(MM, DD, DD, h, Wk + wOff, nullptr, nullptr, kb);
        sgemm<false, false, false><<<gD, 256>>>(MM, DD, DD, h, Wv + wOff, nullptr, nullptr, vb);

        attn_kernel<<<BB * HH, 256>>>(qb, kb, vb, ob);

        // x = x + o @ Wo + bo
        sgemm<false, true, true><<<gD, 256>>>(MM, DD, DD, ob, Wo + wOff, bo + l * DD, x, x);

        ln_kernel<<<MM, 128>>>(x, ln2g + l * DD, ln2b + l * DD, h);

        // hid = gelu(h @ W1 + b1)
        sgemm<true, false, true><<<gF, 256>>>(MM, DFF, DD, h, W1 + w1Off, b1 + l * DFF, nullptr, hid);

        // x = x + hid @ W2 + b2
        sgemm<false, true, true><<<gD, 256>>>(MM, DD, DFF, hid, W2 + w2Off, b2 + l * DD, x, x);
    }

    ln_kernel<<<MM, 128>>>(x, lnfg, lnfb, h);
    unembed_kernel<<<MM, 128>>>(h, Wu, bu, lg);
    loss_kernel<<<MM / 4, 128>>>(lg, tgt);

    int nlog = MM * VV;
    int ncopy = out_size < nlog ? out_size : nlog;
    if (ncopy > 0)
        copy_out_kernel<<<(ncopy + 255) / 256, 256>>>(lg, out, ncopy);
    if (out_size > nlog) {
        int tail = out_size - nlog;
        write_loss_kernel<<<(tail + 127) / 128, 128>>>(out, nlog, out_size);
    }
}

// round 3
// speedup vs baseline: 2.1409x; 2.1409x over previous
#include <cuda_runtime.h>
#include <cuda_bf16.h>
#include <math.h>
#include <stdint.h>

// Problem constants
#define LL   8
#define DD   512
#define HH   8
#define DHH  64
#define SS   64
#define VV   66
#define BB   256
#define MM   (BB * SS)      // 16384 token rows
#define DFF  (4 * DD)       // 2048
#define K3D  (3 * DD)       // 1536  (tripled K for D-sized inputs)
#define K3F  (3 * DFF)      // 6144  (tripled K for hid inputs)

// ---------------- scratch (static device allocations; no cudaMalloc) -------
__device__ float g_x[(size_t)MM * DD];
__device__ float g_h[(size_t)MM * DD];
__device__ float g_qkv[(size_t)MM * K3D];           // fp32 qkv output [M, 1536]
__device__ __nv_bfloat16 g_hA[(size_t)MM * K3D];    // triple-bf16 LN out [hi|lo|hi]
__device__ __nv_bfloat16 g_oA[(size_t)MM * K3D];    // triple-bf16 attn out
__device__ __nv_bfloat16 g_hidA[(size_t)MM * K3F];  // triple-bf16 gelu out
__device__ float g_logits[(size_t)MM * VV];
__device__ float g_loss;

// triple-bf16 transposed weights [N rows][3K cols], layout [hi|hi|lo]
__device__ __nv_bfloat16 g_Wqkv[(size_t)LL * K3D * K3D];        // [1536][1536]
__device__ __nv_bfloat16 g_WoT [(size_t)LL * DD * K3D];         // [512][1536]
__device__ __nv_bfloat16 g_W1T [(size_t)LL * DFF * K3D];        // [2048][1536]
__device__ __nv_bfloat16 g_W2T [(size_t)LL * DD * K3F];         // [512][6144]

// ============================ PTX helpers ===================================
__device__ __forceinline__ uint32_t smem_u32(const void* p) {
    uint32_t a;
    asm("{ .reg .u64 t; cvta.to.shared.u64 t, %1; cvt.u32.u64 %0, t; }"
        : "=r"(a) : "l"(p));
    return a;
}
__device__ __forceinline__ void cp16(uint32_t s, const void* g) {
    asm volatile("cp.async.cg.shared.global [%0], [%1], 16;" :: "r"(s), "l"(g));
}
__device__ __forceinline__ void cp_commit() {
    asm volatile("cp.async.commit_group;" ::: "memory");
}
template<int N>
__device__ __forceinline__ void cp_wait() {
    asm volatile("cp.async.wait_group %0;" :: "n"(N) : "memory");
}
__device__ __forceinline__ void ldsm4(uint32_t* r, uint32_t addr) {
    asm volatile("ldmatrix.sync.aligned.m8n8.x4.shared.b16 {%0,%1,%2,%3}, [%4];"
        : "=r"(r[0]), "=r"(r[1]), "=r"(r[2]), "=r"(r[3]) : "r"(addr));
}
__device__ __forceinline__ void mma16816(float* d, const uint32_t* a, uint32_t b0, uint32_t b1) {
    asm volatile(
        "mma.sync.aligned.m16n8k16.row.col.f32.bf16.bf16.f32 "
        "{%0,%1,%2,%3}, {%4,%5,%6,%7}, {%8,%9}, {%0,%1,%2,%3};"
        : "+f"(d[0]), "+f"(d[1]), "+f"(d[2]), "+f"(d[3])
        : "r"(a[0]), "r"(a[1]), "r"(a[2]), "r"(a[3]), "r"(b0), "r"(b1));
}

// ============================ HMMA GEMM =====================================
// C[M,N] = A'[M,K3] @ B'[N,K3]^T, both triple-bf16 K-major.
// CTA tile 128x128, BK=64, 8 warps (2m x 4n), each warp 64x32.
// EPI 0: C fp32
// EPI 1: C = acc + bias + res   (fp32, res==C aliasing ok)
// EPI 2: C3 = triple-bf16(gelu(acc + bias)), activation layout [hi|lo|hi]
template<int EPI>
__global__ void __launch_bounds__(256, 1)
gemm_mma(const __nv_bfloat16* __restrict__ A, int lda,
         const __nv_bfloat16* __restrict__ B, int ldb,
         int K3,
         float* __restrict__ C, int ldc,
         const float* __restrict__ bias,
         float* __restrict__ res,
         __nv_bfloat16* __restrict__ C3, int kseg)
{
    extern __shared__ char smem[];          // 2 buffers x (A 16KB + B 16KB)
    const int t    = threadIdx.x;
    const int wid  = t >> 5, lane = t & 31;
    const int brow = blockIdx.y * 128;
    const int bcol = blockIdx.x * 128;
    const int wm   = (wid & 1) * 64;        // warp m offset within tile
    const int wn   = (wid >> 1) * 32;       // warp n offset within tile

    uint32_t sbase = smem_u32(smem);

    float acc[4][4][4];
    #pragma unroll
    for (int i = 0; i < 4; i++)
        #pragma unroll
        for (int j = 0; j < 4; j++)
            #pragma unroll
            for (int e = 0; e < 4; e++) acc[i][j][e] = 0.0f;

    // ---- stage loader: A 128x64 + B 128x64 bf16, SW128 swizzle -------------
    auto load_stage = [&](int s) {
        int buf = s & 1;
        int k0  = s << 6;
        uint32_t sa = sbase + buf * 32768u;
        uint32_t sb = sa + 16384u;
        #pragma unroll
        for (int i = 0; i < 4; i++) {
            int c   = t + (i << 8);      // 0..1023
            int row = c >> 3;
            int c16 = c & 7;
            uint32_t off = (uint32_t)(row * 128 + c16 * 16);
            off ^= (off >> 3) & 0x70u;
            cp16(sa + off, A + (size_t)(brow + row) * lda + k0 + c16 * 8);
            cp16(sb + off, B + (size_t)(bcol + row) * ldb + k0 + c16 * 8);
        }
        cp_commit();
    };

    const int S = K3 >> 6;

    // per-lane ldmatrix addressing (relative to tile base, before swizzle):
    // row_in_16 = (lane>>3 & 1)*8 + (lane&7), khalf = (lane>>4)*16 bytes
    const int lrow = ((lane >> 3) & 1) * 8 + (lane & 7);
    const int lkb  = (lane >> 4) * 16;

    load_stage(0);
    for (int s = 0; s < S; s++) {
        int buf = s & 1;
        if (s + 1 < S) { load_stage(s + 1); cp_wait<1>(); }
        else           { cp_wait<0>(); }
        __syncthreads();

        uint32_t sa = sbase + buf * 32768u;
        uint32_t sb = sa + 16384u;

        #pragma unroll
        for (int kk = 0; kk < 4; kk++) {
            int kbyte = kk * 32 + lkb;

            uint32_t afr[4][4];
            #pragma unroll
            for (int mi = 0; mi < 4; mi++) {
                uint32_t off = (uint32_t)((wm + mi * 16 + lrow) * 128 + kbyte);
                off ^= (off >> 3) & 0x70u;
                ldsm4(afr[mi], sa + off);
            }
            uint32_t bfr[2][4];
            #pragma unroll
            for (int nj = 0; nj < 2; nj++) {
                uint32_t off = (uint32_t)((wn + nj * 16 + lrow) * 128 + kbyte);
                off ^= (off >> 3) & 0x70u;
                ldsm4(bfr[nj], sb + off);
            }
            #pragma unroll
            for (int mi = 0; mi < 4; mi++) {
                #pragma unroll
                for (int nj = 0; nj < 2; nj++) {
                    mma16816(acc[mi][2 * nj],     afr[mi], bfr[nj][0], bfr[nj][2]);
                    mma16816(acc[mi][2 * nj + 1], afr[mi], bfr[nj][1], bfr[nj][3]);
                }
            }
        }
        __syncthreads();
    }

    // ---- epilogue (register-resident mma layout) ----------------------------
    #pragma unroll
    for (int mi = 0; mi < 4; mi++) {
        #pragma unroll
        for (int ni = 0; ni < 4; ni++) {
            int r0 = brow + wm + mi * 16 + (lane >> 2);
            int c0 = bcol + wn + ni * 8 + ((lane & 3) << 1);
            #pragma unroll
            for (int half = 0; half < 2; half++) {
                int row = r0 + half * 8;
                float v0 = acc[mi][ni][half * 2];
                float v1 = acc[mi][ni][half * 2 + 1];
                if (EPI == 0) {
                    float2 o = make_float2(v0, v1);
                    *(float2*)&C[(size_t)row * ldc + c0] = o;
                } else if (EPI == 1) {
                    float2 r = *(const float2*)&res[(size_t)row * ldc + c0];
                    float2 o = make_float2(v0 + bias[c0] + r.x,
                                           v1 + bias[c0 + 1] + r.y);
                    *(float2*)&C[(size_t)row * ldc + c0] = o;
                } else {
                    float a0 = v0 + bias[c0];
                    float a1 = v1 + bias[c0 + 1];
                    float g0 = 0.5f * a0 * (1.0f + erff(a0 * 0.70710678118654752f));
                    float g1 = 0.5f * a1 * (1.0f + erff(a1 * 0.70710678118654752f));
                    __nv_bfloat16 h0 = __float2bfloat16(g0);
                    __nv_bfloat16 l0 = __float2bfloat16(g0 - __bfloat162float(h0));
                    __nv_bfloat16 h1 = __float2bfloat16(g1);
                    __nv_bfloat16 l1 = __float2bfloat16(g1 - __bfloat162float(h1));
                    size_t ro = (size_t)row * (3 * kseg);
                    *(__nv_bfloat162*)&C3[ro + c0]            = __nv_bfloat162(h0, h1);
                    *(__nv_bfloat162*)&C3[ro + kseg + c0]     = __nv_bfloat162(l0, l1);
                    *(__nv_bfloat162*)&C3[ro + 2 * kseg + c0] = __nv_bfloat162(h0, h1);
                }
            }
        }
    }
}

// ============================ weight prep ===================================
// W[K,N] fp32 -> out[N][3K] bf16 triple [hi|hi|lo], tiled transpose
__global__ void __launch_bounds__(256) prep_w_kernel(
    const float* __restrict__ W, int K, int N, __nv_bfloat16* __restrict__ out)
{
    __shared__ float ts[32][33];
    int k0 = blockIdx.x * 32, n0 = blockIdx.y * 32;
    int tx = threadIdx.x, ty = threadIdx.y;   // 32 x 8
    #pragma unroll
    for (int i = 0; i < 32; i += 8)
        ts[ty + i][tx] = W[(size_t)(k0 + ty + i) * N + n0 + tx];
    __syncthreads();
    #pragma unroll
    for (int i = 0; i < 32; i += 8) {
        int n = n0 + ty + i, k = k0 + tx;
        float w = ts[tx][ty + i];
        __nv_bfloat16 hi = __float2bfloat16(w);
        __nv_bfloat16 lo = __float2bfloat16(w - __bfloat162float(hi));
        size_t ro = (size_t)n * (3 * K);
        out[ro + k]         = hi;
        out[ro + K + k]     = hi;
        out[ro + 2 * K + k] = lo;
    }
}

// ---------------- embedding + loss reset ------------------------------------
__global__ void __launch_bounds__(256) embed_kernel(
    const int* __restrict__ ids, const float* __restrict__ tok,
    const float* __restrict__ pos, float* __restrict__ x)
{
    int i = blockIdx.x * 256 + threadIdx.x;
    if (i == 0) g_loss = 0.0f;
    if (i >= MM * DD) return;
    int row = i / DD;
    int d   = i - row * DD;
    int s   = row % SS;
    x[i] = tok[(size_t)ids[row] * DD + d] + pos[(size_t)s * DD + d];
}

// ---------------- LayerNorm core (unbiased std, eps on std) -----------------
__device__ __forceinline__ void ln_stats(const float4& v, int t, float& mean, float& inv)
{
    float s  = v.x + v.y + v.z + v.w;
    float ss = v.x * v.x + v.y * v.y + v.z * v.z + v.w * v.w;
    #pragma unroll
    for (int o = 16; o; o >>= 1) {
        s  += __shfl_xor_sync(0xffffffffu, s,  o);
        ss += __shfl_xor_sync(0xffffffffu, ss, o);
    }
    __shared__ float sh[8];
    int wid = t >> 5, lane = t & 31;
    if (lane == 0) { sh[wid * 2] = s; sh[wid * 2 + 1] = ss; }
    __syncthreads();
    s  = sh[0] + sh[2] + sh[4] + sh[6];
    ss = sh[1] + sh[3] + sh[5] + sh[7];
    mean = s * (1.0f / DD);
    float var = (ss - s * mean) * (1.0f / (DD - 1));
    inv = 1.0f / (sqrtf(fmaxf(var, 0.0f)) + 1e-10f);
}

__global__ void __launch_bounds__(128) ln_kernel(
    const float* __restrict__ x, const float* __restrict__ g,
    const float* __restrict__ b, float* __restrict__ out)
{
    int row = blockIdx.x, t = threadIdx.x;
    float4 v = ((const float4*)(x + (size_t)row * DD))[t];
    float mean, inv;
    ln_stats(v, t, mean, inv);
    float4 gv = ((const float4*)g)[t], bv = ((const float4*)b)[t];
    float4 ov;
    ov.x = (v.x - mean) * inv * gv.x + bv.x;
    ov.y = (v.y - mean) * inv * gv.y + bv.y;
    ov.z = (v.z - mean) * inv * gv.z + bv.z;
    ov.w = (v.w - mean) * inv * gv.w + bv.w;
    ((float4*)(out + (size_t)row * DD))[t] = ov;
}

// LN -> triple bf16 [hi|lo|hi], row stride 1536
__global__ void __launch_bounds__(128) ln_triple_kernel(
    const float* __restrict__ x, const float* __restrict__ g,
    const float* __restrict__ b, __nv_bfloat16* __restrict__ out)
{
    int row = blockIdx.x, t = threadIdx.x;
    float4 v = ((const float4*)(x + (size_t)row * DD))[t];
    float mean, inv;
    ln_stats(v, t, mean, inv);
    float4 gv = ((const float4*)g)[t], bv = ((const float4*)b)[t];
    float o[4] = {
        (v.x - mean) * inv * gv.x + bv.x,
        (v.y - mean) * inv * gv.y + bv.y,
        (v.z - mean) * inv * gv.z + bv.z,
        (v.w - mean) * inv * gv.w + bv.w };
    size_t ro = (size_t)row * K3D + t * 4;
    #pragma unroll
    for (int j = 0; j < 4; j++) {
        __nv_bfloat16 hi = __float2bfloat16(o[j]);
        __nv_bfloat16 lo = __float2bfloat16(o[j] - __bfloat162float(hi));
        out[ro + j]            = hi;
        out[ro + DD + j]       = lo;
        out[ro + 2 * DD + j]   = hi;
    }
}

// ---------------- fused causal attention per (b,h) --------------------------
// reads qkv fp32 [M,1536] (q|k|v), writes triple-bf16 o' [M,1536] = [hi|lo|hi]
__global__ void __launch_bounds__(256) attn_kernel(
    const float* __restrict__ qkv, __nv_bfloat16* __restrict__ oA)
{
    int bh = blockIdx.x;
    int b  = bh >> 3;
    int h  = bh & 7;
    const float* qb = qkv + (size_t)b * SS * K3D + h * DHH;
    const float* kb = qb + DD;
    const float* vb = qb + 2 * DD;
    __nv_bfloat16* ob = oA + (size_t)b * SS * K3D + h * DHH;

    __shared__ float Ks[SS][DHH + 1];
    __shared__ float Vs[SS][DHH + 1];
    __shared__ float attn_s[8][SS];

    int tid = threadIdx.x;
    for (int i = tid; i < SS * DHH; i += 256) {
        int s = i >> 6, e = i & 63;
        Ks[s][e] = kb[(size_t)s * K3D + e];
        Vs[s][e] = vb[(size_t)s * K3D + e];
    }
    __syncthreads();

    int warp = tid >> 5, lane = tid & 31;
    const float scale = 0.044194173824159216f;  // 1/sqrt(512)

    for (int r = 0; r < 8; r++) {
        int s = warp * 8 + r;
        float q0 = qb[(size_t)s * K3D + lane];
        float q1 = qb[(size_t)s * K3D + lane + 32];

        float sc0 = 0.0f, sc1 = 0.0f;
        #pragma unroll
        for (int e = 0; e < 32; e++) {
            float qe = __shfl_sync(0xffffffffu, q0, e);
            sc0 = fmaf(qe, Ks[lane][e],      sc0);
            sc1 = fmaf(qe, Ks[lane + 32][e], sc1);
        }
        #pragma unroll
        for (int e = 0; e < 32; e++) {
            float qe = __shfl_sync(0xffffffffu, q1, e);
            sc0 = fmaf(qe, Ks[lane][e + 32],      sc0);
            sc1 = fmaf(qe, Ks[lane + 32][e + 32], sc1);
        }
        sc0 = (lane <= s)      ? sc0 * scale : -1e30f;
        sc1 = (lane + 32 <= s) ? sc1 * scale : -1e30f;

        float m = fmaxf(sc0, sc1);
        #pragma unroll
        for (int off = 16; off; off >>= 1)
            m = fmaxf(m, __shfl_xor_sync(0xffffffffu, m, off));
        float e0 = __expf(sc0 - m), e1 = __expf(sc1 - m);
        float sum = e0 + e1;
        #pragma unroll
        for (int off = 16; off; off >>= 1)
            sum += __shfl_xor_sync(0xffffffffu, sum, off);
        float invs = 1.0f / sum;
        attn_s[warp][lane]      = e0 * invs;
        attn_s[warp][lane + 32] = e1 * invs;
        __syncwarp();

        float o0 = 0.0f, o1 = 0.0f;
        #pragma unroll
        for (int tt = 0; tt < SS; tt++) {
            float a = attn_s[warp][tt];
            o0 = fmaf(a, Vs[tt][lane],      o0);
            o1 = fmaf(a, Vs[tt][lane + 32], o1);
        }
        size_t ro = (size_t)s * K3D;
        __nv_bfloat16 h0 = __float2bfloat16(o0);
        __nv_bfloat16 l0 = __float2bfloat16(o0 - __bfloat162float(h0));
        __nv_bfloat16 h1 = __float2bfloat16(o1);
        __nv_bfloat16 l1 = __float2bfloat16(o1 - __bfloat162float(h1));
        ob[ro + lane]               = h0;
        ob[ro + DD + lane]          = l0;
        ob[ro + 2 * DD + lane]      = h0;
        ob[ro + lane + 32]          = h1;
        ob[ro + DD + lane + 32]     = l1;
        ob[ro + 2 * DD + lane + 32] = h1;
        __syncwarp();
    }
}

// ---------------- unembed: logits = x @ Wu + bu -----------------------------
__global__ void __launch_bounds__(128) unembed_kernel(
    const float* __restrict__ x, const float* __restrict__ Wu,
    const float* __restrict__ bu, float* __restrict__ logits)
{
    __shared__ float xs[DD];
    int row = blockIdx.x;
    for (int i = threadIdx.x; i < DD; i += 128)
        xs[i] = x[(size_t)row * DD + i];
    __syncthreads();
    int n = threadIdx.x;
    if (n < VV) {
        float acc = bu[n];
        #pragma unroll 8
        for (int kk = 0; kk < DD; kk++)
            acc = fmaf(xs[kk], Wu[(size_t)kk * VV + n], acc);
        logits[(size_t)row * VV + n] = acc;
    }
}

// ---------------- cross-entropy loss ----------------------------------------
__global__ void __launch_bounds__(128) loss_kernel(
    const float* __restrict__ logits, const int* __restrict__ tgt)
{
    int warp = threadIdx.x >> 5, lane = threadIdx.x & 31;
    int row  = blockIdx.x * 4 + warp;
    const float* lr = logits + (size_t)row * VV;

    float l0 = lr[lane];
    float l1 = lr[lane + 32];
    float l2 = (lane + 64 < VV) ? lr[lane + 64] : -1e30f;

    float m = fmaxf(fmaxf(l0, l1), l2);
    #pragma unroll
    for (int off = 16; off; off >>= 1)
        m = fmaxf(m, __shfl_xor_sync(0xffffffffu, m, off));
    float sum = expf(l0 - m) + expf(l1 - m) + ((lane + 64 < VV) ? expf(l2 - m) : 0.0f);
    #pragma unroll
    for (int off = 16; off; off >>= 1)
        sum += __shfl_xor_sync(0xffffffffu, sum, off);

    if (lane == 0) {
        float lse = m + logf(sum);
        float lt  = lr[tgt[row]];
        atomicAdd(&g_loss, lse - lt);
    }
}

// ---------------- output assembly -------------------------------------------
__global__ void __launch_bounds__(256) copy_out_kernel(
    const float* __restrict__ lg, float* __restrict__ out, int n)
{
    int i = blockIdx.x * 256 + threadIdx.x;
    if (i < n) out[i] = lg[i];
}
__global__ void __launch_bounds__(128) write_loss_kernel(
    float* __restrict__ out, int lo, int hi)
{
    int i = lo + blockIdx.x * 128 + threadIdx.x;
    if (i < hi) out[i] = g_loss * (1.0f / (float)MM);
}

// ---------------- launcher ----------------------------------------------------
#define GSMEM 65536

extern "C" void kernel_launch(void* const* d_in, const int* in_sizes, int n_in,
                              void* d_out, int out_size)
{
    const int*   ids  = (const int*)d_in[0];
    const int*   tgt  = (const int*)d_in[1];
    const float* tok  = (const float*)d_in[2];
    const float* pos  = (const float*)d_in[3];
    const float* Wq   = (const float*)d_in[4];
    const float* Wk   = (const float*)d_in[5];
    const float* Wv   = (const float*)d_in[6];
    const float* Wo   = (const float*)d_in[7];
    const float* bo   = (const float*)d_in[8];
    const float* W1   = (const float*)d_in[9];
    const float* b1   = (const float*)d_in[10];
    const float* W2   = (const float*)d_in[11];
    const float* b2   = (const float*)d_in[12];
    const float* ln1g = (const float*)d_in[13];
    const float* ln1b = (const float*)d_in[14];
    const float* ln2g = (const float*)d_in[15];
    const float* ln2b = (const float*)d_in[16];
    const float* lnfg = (const float*)d_in[17];
    const float* lnfb = (const float*)d_in[18];
    const float* Wu   = (const float*)d_in[19];
    const float* bu   = (const float*)d_in[20];
    float* out = (float*)d_out;

    float *x, *h, *qkv, *lg;
    __nv_bfloat16 *hA, *oA, *hidA, *Wqkv, *WoT, *W1T, *W2T;
    cudaGetSymbolAddress((void**)&x,    g_x);
    cudaGetSymbolAddress((void**)&h,    g_h);
    cudaGetSymbolAddress((void**)&qkv,  g_qkv);
    cudaGetSymbolAddress((void**)&hA,   g_hA);
    cudaGetSymbolAddress((void**)&oA,   g_oA);
    cudaGetSymbolAddress((void**)&hidA, g_hidA);
    cudaGetSymbolAddress((void**)&lg,   g_logits);
    cudaGetSymbolAddress((void**)&Wqkv, g_Wqkv);
    cudaGetSymbolAddress((void**)&WoT,  g_WoT);
    cudaGetSymbolAddress((void**)&W1T,  g_W1T);
    cudaGetSymbolAddress((void**)&W2T,  g_W2T);

    cudaFuncSetAttribute(gemm_mma<0>, cudaFuncAttributeMaxDynamicSharedMemorySize, GSMEM);
    cudaFuncSetAttribute(gemm_mma<1>, cudaFuncAttributeMaxDynamicSharedMemorySize, GSMEM);
    cudaFuncSetAttribute(gemm_mma<2>, cudaFuncAttributeMaxDynamicSharedMemorySize, GSMEM);

    // ---- weight prep (triple-bf16 transposed) ----
    dim3 pb(32, 8);
    for (int l = 0; l < LL; l++) {
        // QKV concat: out rows [0,512)=Wq, [512,1024)=Wk, [1024,1536)=Wv
        prep_w_kernel<<<dim3(DD/32, DD/32), pb>>>(Wq + (size_t)l*DD*DD, DD, DD,
            Wqkv + (size_t)l*K3D*K3D);
        prep_w_kernel<<<dim3(DD/32, DD/32), pb>>>(Wk + (size_t)l*DD*DD, DD, DD,
            Wqkv + (size_t)l*K3D*K3D + (size_t)DD*K3D);
        prep_w_kernel<<<dim3(DD/32, DD/32), pb>>>(Wv + (size_t)l*DD*DD, DD, DD,
            Wqkv + (size_t)l*K3D*K3D + (size_t)2*DD*K3D);
        prep_w_kernel<<<dim3(DD/32, DD/32), pb>>>(Wo + (size_t)l*DD*DD, DD, DD,
            WoT + (size_t)l*DD*K3D);
        prep_w_kernel<<<dim3(DD/32, DFF/32), pb>>>(W1 + (size_t)l*DD*DFF, DD, DFF,
            W1T + (size_t)l*DFF*K3D);
        prep_w_kernel<<<dim3(DFF/32, DD/32), pb>>>(W2 + (size_t)l*DFF*DD, DFF, DD,
            W2T + (size_t)l*DD*K3F);
    }

    embed_kernel<<<(MM * DD + 255) / 256, 256>>>(ids, tok, pos, x);

    for (int l = 0; l < LL; l++) {
        ln_triple_kernel<<<MM, 128>>>(x, ln1g + l * DD, ln1b + l * DD, hA);

        // qkv = hA @ Wqkv^T   [M,1536] fp32
        gemm_mma<0><<<dim3(K3D/128, MM/128), 256, GSMEM>>>(
            hA, K3D, Wqkv + (size_t)l*K3D*K3D, K3D, K3D,
            qkv, K3D, nullptr, nullptr, nullptr, 0);

        attn_kernel<<<BB * HH, 256>>>(qkv, oA);

        // x = x + o @ Wo + bo
        gemm_mma<1><<<dim3(DD/128, MM/128), 256, GSMEM>>>(
            oA, K3D, WoT + (size_t)l*DD*K3D, K3D, K3D,
            x, DD, bo + l * DD, x, nullptr, 0);

        ln_triple_kernel<<<MM, 128>>>(x, ln2g + l * DD, ln2b + l * DD, hA);

        // hidA = triple_bf16(gelu(hA @ W1^T + b1))
        gemm_mma<2><<<dim3(DFF/128, MM/128), 256, GSMEM>>>(
            hA, K3D, W1T + (size_t)l*DFF*K3D, K3D, K3D,
            nullptr, 0, b1 + l * DFF, nullptr, hidA, DFF);

        // x = x + hid @ W2 + b2
        gemm_mma<1><<<dim3(DD/128, MM/128), 256, GSMEM>>>(
            hidA, K3F, W2T + (size_t)l*DD*K3F, K3F, K3F,
            x, DD, b2 + l * DD, x, nullptr, 0);
    }

    ln_kernel<<<MM, 128>>>(x, lnfg, lnfb, h);
    unembed_kernel<<<MM, 128>>>(h, Wu, bu, lg);
    loss_kernel<<<MM / 4, 128>>>(lg, tgt);

    int nlog = MM * VV;
    int ncopy = out_size < nlog ? out_size : nlog;
    if (ncopy > 0)
        copy_out_kernel<<<(ncopy + 255) / 256, 256>>>(lg, out, ncopy);
    if (out_size > nlog) {
        int tail = out_size - nlog;
        write_loss_kernel<<<(tail + 127) / 128, 128>>>(out, nlog, out_size);
    }
}